// round 17
// baseline (speedup 1.0000x reference)
#include <cuda_runtime.h>
#include <float.h>

#define BB 4096
#define NN 2048
#define NPAIR 3
#define ROW_THREADS 256
#define RED_THREADS 1024

// Per-(pair,row) weighted contributions. Deterministic fixed-order final sum.
__device__ float g_partials[NPAIR * BB];

// 128-bit streaming load (evict-first): data is read exactly once.
__device__ __forceinline__ float4 ldg128_cs(const float4* __restrict__ p) {
    float4 v;
    asm volatile("ld.global.cs.v4.f32 {%0,%1,%2,%3}, [%4];"
                 : "=f"(v.x), "=f"(v.y), "=f"(v.z), "=f"(v.w)
                 : "l"(p));
    return v;
}

__global__ __launch_bounds__(ROW_THREADS)
void wnrmse_row_kernel(const float* __restrict__ o1, const float* __restrict__ t1,
                       const float* __restrict__ o2, const float* __restrict__ t2,
                       const float* __restrict__ o3, const float* __restrict__ t3) {
    const int b = blockIdx.x;   // batch row
    const int p = blockIdx.y;   // pair index
    const int tid = threadIdx.x;

    const float* o = (p == 0) ? o1 : ((p == 1) ? o2 : o3);
    const float* t = (p == 0) ? t1 : ((p == 1) ? t2 : t3);

    const float4* __restrict__ o4 = reinterpret_cast<const float4*>(o + (size_t)b * NN);
    const float4* __restrict__ t4 = reinterpret_cast<const float4*>(t + (size_t)b * NN);

    // 2048 floats = 512 float4; 256 threads -> 2 float4 each. Front-batch all 4 loads.
    float4 ov0 = ldg128_cs(o4 + tid);
    float4 tv0 = ldg128_cs(t4 + tid);
    float4 ov1 = ldg128_cs(o4 + tid + ROW_THREADS);
    float4 tv1 = ldg128_cs(t4 + tid + ROW_THREADS);

    float ssq = 0.0f, tmax = -FLT_MAX, tmin = FLT_MAX;
    {
        float d;
        d = ov0.x - tv0.x; ssq = fmaf(d, d, ssq); tmax = fmaxf(tmax, tv0.x); tmin = fminf(tmin, tv0.x);
        d = ov0.y - tv0.y; ssq = fmaf(d, d, ssq); tmax = fmaxf(tmax, tv0.y); tmin = fminf(tmin, tv0.y);
        d = ov0.z - tv0.z; ssq = fmaf(d, d, ssq); tmax = fmaxf(tmax, tv0.z); tmin = fminf(tmin, tv0.z);
        d = ov0.w - tv0.w; ssq = fmaf(d, d, ssq); tmax = fmaxf(tmax, tv0.w); tmin = fminf(tmin, tv0.w);
        d = ov1.x - tv1.x; ssq = fmaf(d, d, ssq); tmax = fmaxf(tmax, tv1.x); tmin = fminf(tmin, tv1.x);
        d = ov1.y - tv1.y; ssq = fmaf(d, d, ssq); tmax = fmaxf(tmax, tv1.y); tmin = fminf(tmin, tv1.y);
        d = ov1.z - tv1.z; ssq = fmaf(d, d, ssq); tmax = fmaxf(tmax, tv1.z); tmin = fminf(tmin, tv1.z);
        d = ov1.w - tv1.w; ssq = fmaf(d, d, ssq); tmax = fmaxf(tmax, tv1.w); tmin = fminf(tmin, tv1.w);
    }

    // Intra-warp reduce
    #pragma unroll
    for (int s = 16; s > 0; s >>= 1) {
        ssq  += __shfl_xor_sync(0xFFFFFFFFu, ssq,  s);
        tmax  = fmaxf(tmax, __shfl_xor_sync(0xFFFFFFFFu, tmax, s));
        tmin  = fminf(tmin, __shfl_xor_sync(0xFFFFFFFFu, tmin, s));
    }

    // Cross-warp reduce (8 warps)
    __shared__ float s_ssq[8], s_max[8], s_min[8];
    const int w = tid >> 5, l = tid & 31;
    if (l == 0) { s_ssq[w] = ssq; s_max[w] = tmax; s_min[w] = tmin; }
    __syncthreads();

    if (tid == 0) {
        float a  = ((s_ssq[0] + s_ssq[1]) + (s_ssq[2] + s_ssq[3]))
                 + ((s_ssq[4] + s_ssq[5]) + (s_ssq[6] + s_ssq[7]));
        float mx = fmaxf(fmaxf(fmaxf(s_max[0], s_max[1]), fmaxf(s_max[2], s_max[3])),
                         fmaxf(fmaxf(s_max[4], s_max[5]), fmaxf(s_max[6], s_max[7])));
        float mn = fminf(fminf(fminf(s_min[0], s_min[1]), fminf(s_min[2], s_min[3])),
                         fminf(fminf(s_min[4], s_min[5]), fminf(s_min[6], s_min[7])));
        const float wgt = (p == 0) ? 0.5f : 0.25f;
        g_partials[p * BB + b] = wgt * sqrtf(a * (1.0f / NN)) / (mx - mn);
    }
}

// Tail: plain launch, 1024 thr x 3 front-batched float4 (best-measured config).
__global__ __launch_bounds__(RED_THREADS)
void wnrmse_reduce_kernel(float* __restrict__ out) {
    const int tid = threadIdx.x;
    const float4* __restrict__ p4 = reinterpret_cast<const float4*>(g_partials);

    float4 v0 = p4[tid];
    float4 v1 = p4[tid + RED_THREADS];
    float4 v2 = p4[tid + 2 * RED_THREADS];

    float s = ((v0.x + v0.y) + (v0.z + v0.w))
            + ((v1.x + v1.y) + (v1.z + v1.w))
            + ((v2.x + v2.y) + (v2.z + v2.w));

    #pragma unroll
    for (int sh = 16; sh > 0; sh >>= 1)
        s += __shfl_xor_sync(0xFFFFFFFFu, s, sh);

    __shared__ float s_part[32];
    const int w = tid >> 5, l = tid & 31;
    if (l == 0) s_part[w] = s;
    __syncthreads();
    if (w == 0) {
        float a = s_part[l];   // exactly 32 warps
        #pragma unroll
        for (int sh = 16; sh > 0; sh >>= 1)
            a += __shfl_xor_sync(0xFFFFFFFFu, a, sh);
        if (l == 0) out[0] = a * (1.0f / BB);
    }
}

extern "C" void kernel_launch(void* const* d_in, const int* in_sizes, int n_in,
                              void* d_out, int out_size) {
    const float* o1 = (const float*)d_in[0];
    const float* t1 = (const float*)d_in[1];
    const float* o2 = (const float*)d_in[2];
    const float* t2 = (const float*)d_in[3];
    const float* o3 = (const float*)d_in[4];
    const float* t3 = (const float*)d_in[5];
    float* out = (float*)d_out;

    dim3 grid(BB, NPAIR);
    wnrmse_row_kernel<<<grid, ROW_THREADS>>>(o1, t1, o2, t2, o3, t3);
    wnrmse_reduce_kernel<<<1, RED_THREADS>>>(out);
}